// round 1
// baseline (speedup 1.0000x reference)
#include <cuda_runtime.h>

// Problem constants
#define IN_SZ   8192
#define OUT_SZ  8192
#define OUT4    (OUT_SZ / 4)            // 2048 float4 columns
// sigmoid(2.0)
#define SIG_TAU 0.8807970779778823f

// Main-kernel tiling
#define THREADS          256
#define COLS4_PER_BLOCK  256            // one float4 column per thread
#define GRID_X           (OUT4 / COLS4_PER_BLOCK)   // 8
#define NSLICE           128            // split-K row slices
#define ROWS_PER_SLICE   (IN_SZ / NSLICE)           // 64

// Deterministic split-K scratch (no atomics -> bitwise-reproducible spikes)
__device__ float g_partial[NSLICE * OUT_SZ];   // 4 MB

// Fused pass over the [IN_SZ, OUT_SZ] plane:
//   - J_out = SIG_TAU * J + x[i]          (elementwise, 512 MB r/w of the 768 MB total)
//   - acc[j] += x[i] * W[i][j]            (split-K partial GEMV, 256 MB read)
__global__ __launch_bounds__(THREADS, 1)
void ostl_main_kernel(const float* __restrict__ x,
                      const float* __restrict__ J,
                      const float* __restrict__ W,
                      float* __restrict__ Jout)
{
    __shared__ float sx[ROWS_PER_SLICE];

    const int c    = blockIdx.x * COLS4_PER_BLOCK + threadIdx.x;  // float4 column
    const int row0 = blockIdx.y * ROWS_PER_SLICE;

    // Stage this slice's x values into shared (broadcast reads later)
    for (int i = threadIdx.x; i < ROWS_PER_SLICE; i += THREADS)
        sx[i] = x[row0 + i];
    __syncthreads();

    const float4* __restrict__ W4 = (const float4*)W;
    const float4* __restrict__ J4 = (const float4*)J;
    float4*       __restrict__ O4 = (float4*)Jout;

    float4 acc = make_float4(0.f, 0.f, 0.f, 0.f);
    int idx = row0 * OUT4 + c;   // max 16,777,215 -> fits int

    #pragma unroll 4
    for (int r = 0; r < ROWS_PER_SLICE; ++r, idx += OUT4) {
        const float xi = sx[r];
        const float4 w = W4[idx];
        const float4 j = J4[idx];

        acc.x = fmaf(xi, w.x, acc.x);
        acc.y = fmaf(xi, w.y, acc.y);
        acc.z = fmaf(xi, w.z, acc.z);
        acc.w = fmaf(xi, w.w, acc.w);

        float4 o;
        o.x = fmaf(SIG_TAU, j.x, xi);
        o.y = fmaf(SIG_TAU, j.y, xi);
        o.z = fmaf(SIG_TAU, j.z, xi);
        o.w = fmaf(SIG_TAU, j.w, xi);
        O4[idx] = o;
    }

    // Deterministic per-slice partial store (coalesced float4)
    ((float4*)g_partial)[blockIdx.y * OUT4 + c] = acc;
}

// Reduce split-K partials, apply LIF cell update, emit u_out and s.
__global__ __launch_bounds__(256, 1)
void ostl_epilogue_kernel(const float* __restrict__ u,
                          float* __restrict__ out_u,
                          float* __restrict__ out_s)
{
    const int j = blockIdx.x * blockDim.x + threadIdx.x;
    if (j >= OUT_SZ) return;

    float I = 0.f;
    #pragma unroll 8
    for (int k = 0; k < NSLICE; ++k)
        I += g_partial[k * OUT_SZ + j];          // coalesced across threads

    const float u_new = fmaf(SIG_TAU, u[j], I);
    const float s     = (u_new - 1.0f) > 0.f ? 1.0f : 0.0f;  // V_TH = 1
    out_u[j] = u_new - s;                        // V_TH - V_RESET = 1
    out_s[j] = s;
}

extern "C" void kernel_launch(void* const* d_in, const int* in_sizes, int n_in,
                              void* d_out, int out_size)
{
    const float* x = (const float*)d_in[0];
    const float* u = (const float*)d_in[1];
    const float* J = (const float*)d_in[2];
    const float* W = (const float*)d_in[3];

    float* out   = (float*)d_out;
    float* out_u = out;                                   // [0, 8192)
    float* out_J = out + OUT_SZ;                          // [8192, 8192+64M)
    float* out_s = out + OUT_SZ + (size_t)IN_SZ * OUT_SZ; // last 8192

    dim3 grid(GRID_X, NSLICE);
    ostl_main_kernel<<<grid, THREADS>>>(x, J, W, out_J);
    ostl_epilogue_kernel<<<OUT_SZ / 256, 256>>>(u, out_u, out_s);
}